// round 17
// baseline (speedup 1.0000x reference)
#include <cuda_runtime.h>
#include <cuda_bf16.h>
#include <cstdint>

#define RES   128
#define FEAT  1024               // map_num * feat_dim
#define NCELL (RES * RES)        // 16384
#define V4    (FEAT / 4)         // 256 float4 per row

#define CAP      64              // slots per cell bucket (Poisson(4) -> P(>64) ~ 0)
#define CAP_LOG2 6

#define PJD   64                 // pair-columns per dim (1x2 cells per block)
#define NPAIR (RES * PJD)        // 128 * 64 = 8192 blocks

// Scratch (allocation-free: __device__ globals, zero-initialized at load).
// Invariant: g_count is all-zero at entry of every kernel_launch call —
// bucket_scatter fills it, zero_count_kernel (last launch) resets it.
__device__ int    g_count[NCELL];
__device__ float4 g_bucket[NCELL * CAP];   // {f0, f1, bitcast(p), 0}

// ---- f32x2 packed-math helpers (sm_103a) ------------------------------
__device__ __forceinline__ uint64_t pack2(float lo, float hi) {
    uint64_t r;
    asm("mov.b64 %0, {%1, %2};" : "=l"(r) : "f"(lo), "f"(hi));
    return r;
}
#define MUL2(d, a, b) \
    asm("mul.rn.f32x2 %0, %1, %2;" : "=l"(d) : "l"(a), "l"(b))
#define FMA2(d, a, b, c) \
    asm("fma.rn.f32x2 %0, %1, %2, %3;" : "=l"(d) : "l"(a), "l"(b), "l"(c))

// Pass 1: bin every point into its cell bucket. ONE point per thread —
// 65536 threads / 512 blocks so every SM holds ~14 warps, each covering a
// single LDG -> ATOMG -> STG latency chain (this kernel is pure latency;
// R16's 2-pt/thread variant halved warp count and was net-neutral).
__global__ void bucket_scatter_kernel(const float* __restrict__ inp, int n) {
    cudaTriggerProgrammaticLaunchCompletion();
    const int p = blockIdx.x * blockDim.x + threadIdx.x;
    if (p < n) {
        const float2 u = __ldg((const float2*)inp + p);
        const float x0 = u.x * (float)(RES - 1);
        const float x1 = u.y * (float)(RES - 1);
        const float fl0 = floorf(x0);
        const float fl1 = floorf(x1);
        const int cell = (int)fl0 * RES + (int)fl1;
        const int pos  = atomicAdd(&g_count[cell], 1);   // < CAP by construction
        g_bucket[(cell << CAP_LOG2) + pos] =
            make_float4(x0 - fl0, x1 - fl1, __int_as_float(p), 0.0f);
    }
}

// Pass 2: one block per 1x2 cell pair.
//  - PDL: the 6 scatter-independent emb row loads are issued before
//    cudaGridDependencySynchronize(); bucket/count reads after.
//  - Row operands packed into f32x2 pairs per cell (loop-invariant); per
//    point the blend is 2x(mul+3fma) f32x2 ops + one st.global.cs.v2.b64.
__global__ void __launch_bounds__(V4, 5)
pair_bilerp_kernel(const float* __restrict__ emb,
                   float* __restrict__ out)
{
    const int ci0 = blockIdx.x >> 6;                 // cell row 0..127
    const int b1  = (blockIdx.x & (PJD - 1)) << 1;   // cell col base, even
    const int c   = threadIdx.x;                     // float4 column 0..255

    // Scatter-independent prologue: 2x3 corner-row patch (6 independent 16B
    // loads in flight while the scatter drains). Clamped far-edge rows are
    // never used (cells with i0==127 or i1==127 are empty).
    float4 r[2][3];
    #pragma unroll
    for (int dr = 0; dr < 2; dr++) {
        #pragma unroll
        for (int dc = 0; dc < 3; dc++) {
            const int i0 = min(ci0 + dr, RES - 1);
            const int i1 = min(b1  + dc, RES - 1);
            r[dr][dc] = __ldg((const float4*)(emb + (size_t)(i0 * RES + i1) * FEAT) + c);
        }
    }

    cudaGridDependencySynchronize();

    // Warm L1 with the first 128B (slots 0..7) of each cell's bucket.
    #pragma unroll
    for (int g = 0; g < 2; g++) {
        const int cell = ci0 * RES + (b1 + g);
        const char* bp = (const char*)(g_bucket + (cell << CAP_LOG2));
        asm volatile("prefetch.global.L1 [%0];" :: "l"(bp));
        asm volatile("prefetch.global.L1 [%0];" :: "l"(bp + 64));
    }

    int cnt[2];
    #pragma unroll
    for (int g = 0; g < 2; g++)
        cnt[g] = __ldg(&g_count[ci0 * RES + (b1 + g)]);

    #pragma unroll
    for (int s1 = 0; s1 < 2; s1++) {
        const int n = cnt[s1];
        if (n == 0) continue;

        const int cell = ci0 * RES + (b1 + s1);
        const float4* __restrict__ bucket = g_bucket + (cell << CAP_LOG2);

        const float4 a = r[0][s1    ];   // (i0,  i1  )
        const float4 b = r[1][s1    ];   // (i0+1,i1  )
        const float4 d = r[0][s1 + 1];   // (i0,  i1+1)
        const float4 e = r[1][s1 + 1];   // (i0+1,i1+1)

        // Loop-invariant packed row operands.
        const uint64_t Axy = pack2(a.x, a.y), Azw = pack2(a.z, a.w);
        const uint64_t Bxy = pack2(b.x, b.y), Bzw = pack2(b.z, b.w);
        const uint64_t Dxy = pack2(d.x, d.y), Dzw = pack2(d.z, d.w);
        const uint64_t Exy = pack2(e.x, e.y), Ezw = pack2(e.z, e.w);

        for (int k = 0; k < n; k++) {
            const float4 pf = bucket[k];              // L1-warm broadcast
            const float f0 = pf.x, f1 = pf.y;
            const int   p  = __float_as_int(pf.z);
            const float g0 = 1.0f - f0, g1 = 1.0f - f1;
            const uint64_t W00 = pack2(g0 * g1, g0 * g1);
            const uint64_t W10 = pack2(f0 * g1, f0 * g1);
            const uint64_t W01 = pack2(g0 * f1, g0 * f1);
            const uint64_t W11 = pack2(f0 * f1, f0 * f1);

            uint64_t oxy, ozw;
            MUL2(oxy, Axy, W00);
            FMA2(oxy, Bxy, W10, oxy);
            FMA2(oxy, Dxy, W01, oxy);
            FMA2(oxy, Exy, W11, oxy);
            MUL2(ozw, Azw, W00);
            FMA2(ozw, Bzw, W10, ozw);
            FMA2(ozw, Dzw, W01, ozw);
            FMA2(ozw, Ezw, W11, ozw);

            float4* dst = (float4*)(out + (size_t)p * FEAT) + c;
            asm volatile("st.global.cs.v2.b64 [%0], {%1, %2};"
                         :: "l"(dst), "l"(oxy), "l"(ozw) : "memory");
        }
    }
}

// Pass 3: reset counters for the next graph replay (PDL removes the gap;
// gridsync orders it after the main kernel's count reads).
__global__ void zero_count_kernel() {
    cudaGridDependencySynchronize();
    const int i = blockIdx.x * blockDim.x + threadIdx.x;
    if (i < NCELL) g_count[i] = 0;
}

extern "C" void kernel_launch(void* const* d_in, const int* in_sizes, int n_in,
                              void* d_out, int out_size)
{
    const float* inp = (const float*)d_in[0];   // [batch, 2]
    const float* emb = (const float*)d_in[1];   // [16384, 1024]
    float* out = (float*)d_out;                 // [batch, 1024]

    const int n_points  = in_sizes[0] / 2;
    const int pt_blocks = (n_points + 127) / 128;   // 512 blocks x 128 thr

    bucket_scatter_kernel<<<pt_blocks, 128>>>(inp, n_points);

    cudaLaunchAttribute attr[1];
    attr[0].id = cudaLaunchAttributeProgrammaticStreamSerialization;
    attr[0].val.programmaticStreamSerializationAllowed = 1;

    {
        cudaLaunchConfig_t cfg = {};
        cfg.gridDim  = dim3(NPAIR);
        cfg.blockDim = dim3(V4);
        cfg.attrs    = attr;
        cfg.numAttrs = 1;
        cudaLaunchKernelEx(&cfg, pair_bilerp_kernel, emb, out);
    }
    {
        cudaLaunchConfig_t cfg = {};
        cfg.gridDim  = dim3((NCELL + 255) / 256);
        cfg.blockDim = dim3(256);
        cfg.attrs    = attr;
        cfg.numAttrs = 1;
        cudaLaunchKernelEx(&cfg, zero_count_kernel);
    }
}